// round 12
// baseline (speedup 1.0000x reference)
#include <cuda_runtime.h>
#include <math.h>

#define Bsz   32
#define Ssz   20
#define Psz   256
#define HIDN  128
#define MIDN  64
#define G2N   16
#define OBSN  8
#define PREDN 12
#define OUTN  5
#define RROWS (Psz*Bsz)          // 8192 rows, r = p*32 + b  (p-major)
#define ZC    (MIDN+HIDN)        // 192
#define XP_ELEMS (Bsz*PREDN*Psz*3)   // 294912

// ---- packed fp32x2 helpers (sm_100+): bit-exact per-lane f32 ops ----
#define PACK2(d, s)      asm("mov.b64 %0, {%1, %1};" : "=l"(d) : "f"(s))
#define UNPACK2(lo,hi,s) asm("mov.b64 {%0, %1}, %2;" : "=f"(lo), "=f"(hi) : "l"(s))
#define FMA2(d, a, b)    asm("fma.rn.f32x2 %0, %1, %2, %0;" : "+l"(d) : "l"(a), "l"(b))
#define ADD2(d, a)       asm("add.rn.f32x2 %0, %0, %1;" : "+l"(d) : "l"(a))

// ---------------- device scratch ----------------
__device__ float g_c[RROWS*HIDN];          // carry (cell state), 4 MB
__device__ float g_o[RROWS*OUTN];          // last output
__device__ float g_Wt[2048*HIDN];          // W_soc transposed [k][n], 1 MB
__device__ float g_Wt2[ZC*384];            // W_ih (i,g,o rows) transposed [k][384]
__device__ unsigned char g_list[Psz*Psz];  // per-p neighbor ids grouped by cell
__device__ int g_off[Psz*(G2N+1)];         // per-p per-cell offsets
__device__ unsigned int g_active[Psz];     // per-p active-cell bitmask

__device__ __forceinline__ float sigf(float x){ return 1.f/(1.f+expf(-x)); }

// ---------------- init carry = relu(b_prev) broadcast ----------------
__global__ void k_init(const float* __restrict__ bprev){
  int i = blockIdx.x*256 + threadIdx.x;
  if (i < RROWS*HIDN){ float v = bprev[i & (HIDN-1)]; g_c[i] = v > 0.f ? v : 0.f; }
}

// ---------------- one-time transpose of W_soc [128][2048] -> g_Wt [2048][128] ----------------
__global__ void k_wt(const float* __restrict__ Wsoc){
  int i = blockIdx.x*256 + threadIdx.x;     // i over 128*2048
  if (i < HIDN*2048){
    int n = i >> 11, k = i & 2047;
    g_Wt[k*HIDN + n] = Wsoc[i];
  }
}

// ---------------- one-time transpose of W_ih (rows i,g,o) -> g_Wt2 [192][384] ----------------
__global__ void k_wt2(const float* __restrict__ Wih){
  int i = blockIdx.x*256 + threadIdx.x;     // i over 192*384
  if (i < ZC*384){
    int k = i / 384, jj = i % 384;
    int row = (jj < 128) ? jj : jj + 128;
    g_Wt2[k*384 + jj] = Wih[(size_t)row*ZC + k];
  }
}

// ---------------- ballot mask: 1 warp per p (R4-proven, ascending-q == serial order) ----------------
__global__ void k_mask(const float* __restrict__ x, int t, int pred){
  __shared__ float qpid[Psz], qpx[Psz], qpy[Psz];
  int tid = threadIdx.x;
  int tx = tid & 31, w = tid >> 5;         // 8 warps, warp = one p
  {
    int q = tid;
    if (pred){
      qpid[q] = x[((size_t)(Ssz-1)*Psz + q)*3 + 0];
      qpx[q]  = g_o[(q*Bsz + 0)*OUTN + 0];
      qpy[q]  = g_o[(q*Bsz + 0)*OUTN + 1];
    } else {
      const float* xb = x + (size_t)(t*Psz)*3;
      qpid[q] = xb[q*3+0]; qpx[q] = xb[q*3+1]; qpy[q] = xb[q*3+2];
    }
  }
  __syncthreads();
  int p = blockIdx.x*8 + w;
  const float CELLF = 0.1f;
  unsigned int lt = (1u << tx) - 1u;
  float pxv = qpx[p], pyv = qpy[p], pidv = qpid[p];
  float lx = pxv-0.2f, rxb = pxv+0.2f, by = pyv-0.2f, tyv = pyv+0.2f;
  unsigned char gr[8];
  #pragma unroll
  for (int c = 0; c < 8; c++){
    int q = c*32 + tx;
    float ox = qpx[q], oy = qpy[q];
    bool inb   = (ox < rxb) && (ox >= lx) && (oy < tyv) && (oy >= by);
    bool valid = (pidv != 0.f) && (qpid[q] != 0.f) && (pidv != qpid[q]);
    int cx = (int)floorf((ox - lx)/CELLF);
    int cy = (int)floorf((oy - by)/CELLF);
    int idx = cx + cy*4; idx = idx < 0 ? 0 : (idx > 15 ? 15 : idx);
    gr[c] = (inb && valid) ? (unsigned char)idx : (unsigned char)255;
  }
  int base = 0; unsigned int act = 0;
  #pragma unroll
  for (int g = 0; g < 16; g++){
    if (tx == 0) g_off[p*17 + g] = base;
    int cum = 0;
    #pragma unroll
    for (int c = 0; c < 8; c++){
      unsigned int m = __ballot_sync(0xffffffffu, gr[c] == (unsigned char)g);
      if (gr[c] == (unsigned char)g)
        g_list[p*Psz + base + cum + __popc(m & lt)] = (unsigned char)(c*32 + tx);
      cum += __popc(m);
    }
    if (cum) act |= (1u << g);
    base += cum;
  }
  if (tx == 0){
    g_off[p*17 + 16] = base;
    g_active[p] = act;
  }
}

// ---- hsum build for one cell: EXACT dual-accumulator even/odd order (bit-exact) ----
__device__ __forceinline__ void build_cell(
    int g, float* __restrict__ hsb, int wl, int tx,
    const float4* __restrict__ cs4,
    const unsigned char* __restrict__ ls,
    const int* __restrict__ offs){
  #pragma unroll
  for (int i2 = 0; i2 < 8; i2++){
    int pl = wl*8 + i2;
    int s = offs[pl*17 + g], e = offs[pl*17 + g + 1];
    unsigned long long a0lo = 0ull, a0hi = 0ull, a1lo = 0ull, a1hi = 0ull;
    int j = s;
    for (; j+1 < e; j += 2){
      ulonglong2 v0 = *(const ulonglong2*)(cs4 + (int)ls[pl*Psz + j]*32 + tx);
      ulonglong2 v1 = *(const ulonglong2*)(cs4 + (int)ls[pl*Psz + j+1]*32 + tx);
      ADD2(a0lo, v0.x); ADD2(a0hi, v0.y);
      ADD2(a1lo, v1.x); ADD2(a1hi, v1.y);
    }
    if (j < e){
      ulonglong2 v0 = *(const ulonglong2*)(cs4 + (int)ls[pl*Psz + j]*32 + tx);
      ADD2(a0lo, v0.x); ADD2(a0hi, v0.y);
    }
    ADD2(a0lo, a1lo); ADD2(a0hi, a1hi);
    *(ulonglong2*)(hsb + pl*132 + tx*4) = make_ulonglong2(a0lo, a0hi);
  }
}

// ---------------- fused: hsum||socGEMM + e + LSTM + output head ----------------
// Block = (b, 64-p tile), 512 threads = 16 warps.
// Phase A: warps 0-7 soc GEMM (FFMA2), warps 8-15 hsum producer (double buffer).
// Phase B: z -> smem; in-block LSTM gate GEMM (k ascending, bit-exact);
//          gates -> g_c + h in smem; B4 output head (exact k_out reduction order).
#define PT     64
#define HS_STR 132
#define ZS_STR 196
#define WS2    388
__global__ void __launch_bounds__(512, 1) k_fused(
    const float* __restrict__ x,
    const float* __restrict__ bsoc,
    const float* __restrict__ Win,
    const float* __restrict__ bin,
    const float* __restrict__ bih,
    const float* __restrict__ bhh,
    const float* __restrict__ Wout,
    const float* __restrict__ bout,
    float* __restrict__ out,
    int t, int pred,
    int wr_o, int wr_op, int kstep, int wr_xp, int xpk){
  extern __shared__ float dyn[];
  float* cs  = dyn;                        // 256*128 floats = 128 KB (phase A)
  float* hs0 = dyn + Psz*HIDN;             // 64*132 floats
  float* hs1 = hs0 + PT*HS_STR;            // 64*132 floats
  // phase B overlays (cs/hs dead):
  float* zs     = dyn;                     // 64*196 floats
  float* wstage = dyn + PT*ZS_STR;         // 16*388 floats
  float* gsum   = wstage + 16*WS2;         // 64*388 floats
  float* hsm    = dyn;                     // 64*128 floats (overlays zs after B2)
  __shared__ unsigned char ls[PT*Psz];     // 16 KB neighbor lists
  __shared__ int offs[PT*(G2N+1)];
  __shared__ int gl[G2N];
  __shared__ int s_ng;

  int b = blockIdx.x, pbase = blockIdx.y*PT;
  int tid = threadIdx.x;
  float4* cs4 = (float4*)cs;

  // load c[:,b,:] (all 256 p rows for this b)
  for (int i = tid; i < Psz*HIDN/4; i += 512){
    int o = i>>5, q = i&31;
    cs4[i] = *(const float4*)(g_c + ((size_t)o*Bsz + b)*HIDN + q*4);
  }
  // neighbor lists + offsets for this p-tile (contiguous copy)
  for (int i = tid; i < PT*Psz/16; i += 512)
    ((uint4*)ls)[i] = ((const uint4*)(g_list + (size_t)pbase*Psz))[i];
  for (int i = tid; i < PT*(G2N+1); i += 512)
    offs[i] = g_off[pbase*(G2N+1) + i];
  if (tid == 0){
    unsigned int u = 0;
    for (int pp = 0; pp < PT; pp++) u |= g_active[pbase+pp];
    int n = 0;
    for (int g = 0; g < G2N; g++) if ((u>>g)&1u) gl[n++] = g;
    s_ng = n;
  }
  __syncthreads();
  int ng = s_ng;

  int tx = tid & 31, wid = tid >> 5;    // 16 warps
  int group = wid >> 3, wl = wid & 7;   // group 0: GEMM, group 1: producer
  int n0 = tx*4, m0 = wl*8;
  unsigned long long acc01[8], acc23[8];
  #pragma unroll
  for (int i = 0; i < 8; i++){ acc01[i] = 0ull; acc23[i] = 0ull; }

  if (ng > 0){
    if (group == 1) build_cell(gl[0], hs0, wl, tx, cs4, ls, offs);
    __syncthreads();
    for (int gi = 0; gi < ng; gi++){
      if (group == 0){
        const float* hsb = (gi & 1) ? hs1 : hs0;
        const float* Wg = g_Wt + (size_t)gl[gi]*128*HIDN + n0;
        #pragma unroll 2
        for (int kc = 0; kc < 8; kc++){
          #pragma unroll
          for (int kq = 0; kq < 4; kq++){
            float4 hv[8];
            #pragma unroll
            for (int i = 0; i < 8; i++)
              hv[i] = *(const float4*)(hsb + (m0+i)*HS_STR + kc*16 + kq*4);
            #pragma unroll
            for (int kk = 0; kk < 4; kk++){
              ulonglong2 wp = *(const ulonglong2*)(Wg + (size_t)(kc*16 + kq*4 + kk)*HIDN);
              #pragma unroll
              for (int i = 0; i < 8; i++){
                float h = ((const float*)&hv[i])[kk];
                unsigned long long h2;
                PACK2(h2, h);
                FMA2(acc01[i], h2, wp.x);
                FMA2(acc23[i], h2, wp.y);
              }
            }
          }
        }
      } else if (gi + 1 < ng){
        build_cell(gl[gi+1], ((gi+1) & 1) ? hs1 : hs0, wl, tx, cs4, ls, offs);
      }
      __syncthreads();
    }
  }

  // ================= Phase B =================
  // B1: e = relu(pos @ Win^T + bin) -> zs[:,0:64]
  for (int i2 = tid; i2 < PT*MIDN; i2 += 512){
    int mm = i2 >> 6, j = i2 & 63;
    int p = pbase + mm;
    int r = p*Bsz + b;
    float px, py;
    if (pred){ px = g_o[r*OUTN+0]; py = g_o[r*OUTN+1]; }
    else {
      const float* xr = x + (size_t)(((b*Ssz)+t)*Psz + p)*3;
      px = xr[1]; py = xr[2];
    }
    float v = px*Win[j*2+0] + py*Win[j*2+1] + bin[j];
    zs[mm*ZS_STR + j] = v > 0.f ? v : 0.f;
  }
  // B1b: a = relu(acc + b_soc) -> zs[:,64:192]
  if (group == 0){
    float4 bv = *(const float4*)(bsoc + n0);
    #pragma unroll
    for (int i = 0; i < 8; i++){
      float a0, a1, a2, a3;
      UNPACK2(a0, a1, acc01[i]);
      UNPACK2(a2, a3, acc23[i]);
      float4 o;
      o.x = fmaxf(a0 + bv.x, 0.f);
      o.y = fmaxf(a1 + bv.y, 0.f);
      o.z = fmaxf(a2 + bv.z, 0.f);
      o.w = fmaxf(a3 + bv.w, 0.f);
      *(float4*)(zs + (m0+i)*ZS_STR + MIDN + n0) = o;
    }
  }
  __syncthreads();

  // B2: LSTM gate GEMM: gsum[row][jj] = sum_{k=0..191} zs[row][k] * Wt2[k][jj]
  {
    int jpg = tid & 63, rowg = tid >> 6;
    int j0 = jpg*6, m2 = rowg*8;
    unsigned long long lacc[24];
    #pragma unroll
    for (int i = 0; i < 24; i++) lacc[i] = 0ull;
    for (int kc = 0; kc < 12; kc++){
      #pragma unroll
      for (int s3 = 0; s3 < 3; s3++){
        int idx = s3*512 + tid;           // 0..1535
        int kk = idx / 96, v4 = idx % 96;
        *(float4*)(wstage + kk*WS2 + v4*4) =
          *(const float4*)(g_Wt2 + (size_t)(kc*16 + kk)*384 + v4*4);
      }
      __syncthreads();
      #pragma unroll 4
      for (int kk = 0; kk < 16; kk++){
        int k = kc*16 + kk;
        unsigned long long h2[8];
        #pragma unroll
        for (int i = 0; i < 8; i++){
          float hv = zs[(m2+i)*ZS_STR + k];
          PACK2(h2[i], hv);
        }
        #pragma unroll
        for (int jj = 0; jj < 3; jj++){
          unsigned long long w2 = *(const unsigned long long*)(wstage + kk*WS2 + j0 + 2*jj);
          #pragma unroll
          for (int i = 0; i < 8; i++)
            FMA2(lacc[i*3+jj], h2[i], w2);
        }
      }
      __syncthreads();
    }
    #pragma unroll
    for (int i = 0; i < 8; i++)
      #pragma unroll
      for (int jj = 0; jj < 3; jj++)
        *(unsigned long long*)(gsum + (m2+i)*WS2 + j0 + 2*jj) = lacc[i*3+jj];
  }
  __syncthreads();

  // B3: gates -> c (always) and h -> hsm (only if output needed)
  for (int idx = tid; idx < PT*HIDN; idx += 512){
    int row = idx >> 7, jH = idx & 127;
    float ai = gsum[row*WS2 + jH];
    float ag = gsum[row*WS2 + 128 + jH];
    float ao = gsum[row*WS2 + 256 + jH];
    float bi_ = bih[jH]       + bhh[jH];
    float bg_ = bih[256 + jH] + bhh[256 + jH];
    float bo_ = bih[384 + jH] + bhh[384 + jH];
    float ci = sigf(ai+bi_)*tanhf(ag+bg_);
    float hh = sigf(ao+bo_)*tanhf(ci);
    int r = (pbase + row)*Bsz + b;
    g_c[(size_t)r*HIDN + jH] = ci;
    if (wr_o) hsm[row*HIDN + jH] = hh;
  }

  // B4: output head o = h @ Wout^T + bout  (EXACT k_out order: 4-term serial + butterfly)
  if (wr_o){
    __syncthreads();
    // 16 warps x 4 rows
    #pragma unroll
    for (int rr = 0; rr < 4; rr++){
      int row = wid*4 + rr;
      float hv[4];
      #pragma unroll
      for (int i = 0; i < 4; i++) hv[i] = hsm[row*HIDN + tx + i*32];
      float res[5];
      #pragma unroll
      for (int c = 0; c < 5; c++){
        float s = 0.f;
        #pragma unroll
        for (int i = 0; i < 4; i++) s += hv[i]*__ldg(Wout + c*HIDN + tx + i*32);
        #pragma unroll
        for (int d = 16; d > 0; d >>= 1) s += __shfl_xor_sync(0xffffffffu, s, d);
        res[c] = s + bout[c];
      }
      if (tx == 0){
        int p = pbase + row;
        int r = p*Bsz + b;
        #pragma unroll
        for (int c = 0; c < 5; c++){
          g_o[r*OUTN + c] = res[c];
          if (wr_op)
            out[(size_t)XP_ELEMS + ((size_t)(b*PREDN + kstep)*Psz + p)*OUTN + c] = res[c];
        }
        if (wr_xp){
          float pid = x[((size_t)(b*Ssz + Ssz-1)*Psz + p)*3 + 0];
          size_t base = ((size_t)(b*PREDN + xpk)*Psz + p)*3;
          out[base+0] = pid;
          out[base+1] = res[0];
          out[base+2] = res[1];
        }
      }
    }
  }
}

// ---------------- launch ----------------
extern "C" void kernel_launch(void* const* d_in, const int* in_sizes, int n_in,
                              void* d_out, int out_size){
  const float* x    = (const float*)d_in[0];
  const float* Win  = (const float*)d_in[1];
  const float* bin  = (const float*)d_in[2];
  const float* Wsoc = (const float*)d_in[3];
  const float* bsoc = (const float*)d_in[4];
  const float* bprev= (const float*)d_in[5];
  const float* Wih  = (const float*)d_in[6];
  const float* bih  = (const float*)d_in[7];
  const float* bhh  = (const float*)d_in[8];
  const float* Wout = (const float*)d_in[9];
  const float* bout = (const float*)d_in[10];
  float* out = (float*)d_out;

  const int DYN_A = (Psz*HIDN + 2*PT*HS_STR)*(int)sizeof(float);
  const int DYN_B = (PT*ZS_STR + 16*WS2 + PT*WS2)*(int)sizeof(float);
  const int DYN = DYN_A > DYN_B ? DYN_A : DYN_B;
  cudaFuncSetAttribute(k_fused, cudaFuncAttributeMaxDynamicSharedMemorySize, DYN);

  k_init<<<(RROWS*HIDN + 255)/256, 256>>>(bprev);
  k_wt<<<(HIDN*2048 + 255)/256, 256>>>(Wsoc);
  k_wt2<<<(ZC*384 + 255)/256, 256>>>(Wih);
  for (int t = 0; t < OBSN; t++){
    k_mask<<<Psz/8, 256>>>(x, t, 0);
    int last = (t == OBSN-1);
    k_fused<<<dim3(Bsz, Psz/PT), 512, DYN>>>(x, bsoc, Win, bin, bih, bhh,
                                             Wout, bout, out, t, 0,
                                             last, 0, 0, last, 0);
  }
  for (int k = 0; k < PREDN; k++){
    k_mask<<<Psz/8, 256>>>(x, 0, 1);
    k_fused<<<dim3(Bsz, Psz/PT), 512, DYN>>>(x, bsoc, Win, bin, bih, bhh,
                                             Wout, bout, out, 0, 1,
                                             1, 1, k, (k < PREDN-1) ? 1 : 0, k+1);
  }
}

// round 13
// speedup vs baseline: 1.0294x; 1.0294x over previous
#include <cuda_runtime.h>
#include <math.h>

#define Bsz   32
#define Ssz   20
#define Psz   256
#define HIDN  128
#define MIDN  64
#define G2N   16
#define OBSN  8
#define PREDN 12
#define OUTN  5
#define RROWS (Psz*Bsz)          // 8192 rows, r = p*32 + b  (p-major)
#define ZC    (MIDN+HIDN)        // 192
#define XP_ELEMS (Bsz*PREDN*Psz*3)   // 294912

// ---- packed fp32x2 helpers (sm_100+): bit-exact per-lane f32 ops ----
#define PACK2(d, s)      asm("mov.b64 %0, {%1, %1};" : "=l"(d) : "f"(s))
#define UNPACK2(lo,hi,s) asm("mov.b64 {%0, %1}, %2;" : "=f"(lo), "=f"(hi) : "l"(s))
#define FMA2(d, a, b)    asm("fma.rn.f32x2 %0, %1, %2, %0;" : "+l"(d) : "l"(a), "l"(b))
#define ADD2(d, a)       asm("add.rn.f32x2 %0, %0, %1;" : "+l"(d) : "l"(a))

// ---------------- device scratch ----------------
__device__ float g_c[RROWS*HIDN];          // carry (cell state), 4 MB
__device__ float g_h[RROWS*HIDN];          // hidden h, 4 MB
__device__ float g_o[RROWS*OUTN];          // last output
__device__ float g_Wt[2048*HIDN];          // W_soc transposed [k][n], 1 MB
__device__ float g_Wt2[ZC*384];            // W_ih (i,g,o rows) transposed [k][384]
__device__ unsigned char g_list[OBSN*Psz*Psz];  // per-slot per-p neighbor ids
__device__ int g_off[OBSN*Psz*17];              // per-slot per-p per-cell offsets
__device__ unsigned int g_active[OBSN*Psz];     // per-slot per-p active bitmask

__device__ __forceinline__ float sigf(float x){ return 1.f/(1.f+expf(-x)); }

// ---------------- init carry = relu(b_prev) broadcast ----------------
__global__ void k_init(const float* __restrict__ bprev){
  int i = blockIdx.x*256 + threadIdx.x;
  if (i < RROWS*HIDN){ float v = bprev[i & (HIDN-1)]; g_c[i] = v > 0.f ? v : 0.f; }
}

// ---------------- one-time transpose of W_soc [128][2048] -> g_Wt [2048][128] ----------------
__global__ void k_wt(const float* __restrict__ Wsoc){
  int i = blockIdx.x*256 + threadIdx.x;     // i over 128*2048
  if (i < HIDN*2048){
    int n = i >> 11, k = i & 2047;
    g_Wt[k*HIDN + n] = Wsoc[i];
  }
}

// ---------------- one-time transpose of W_ih (rows i,g,o) -> g_Wt2 [192][384] ----------------
__global__ void k_wt2(const float* __restrict__ Wih){
  int i = blockIdx.x*256 + threadIdx.x;     // i over 192*384
  if (i < ZC*384){
    int k = i / 384, jj = i % 384;
    int row = (jj < 128) ? jj : jj + 128;
    g_Wt2[k*384 + jj] = Wih[(size_t)row*ZC + k];
  }
}

// ---------------- mask (R0-proven serial scan), slot-indexed ----------------
// grid.y = number of steps batched; t = t_base + blockIdx.y, slot likewise.
__global__ void k_mask(const float* __restrict__ x, int t_base, int pred){
  __shared__ float spid[Psz], spx[Psz], spy[Psz];
  __shared__ unsigned char garr[Psz];
  __shared__ int cnt[G2N], off[G2N+1];
  int p = blockIdx.x, q = threadIdx.x;
  int t = t_base + blockIdx.y;
  int slot = pred ? 0 : t;
  if (pred){
    spid[q] = x[((size_t)(Ssz-1)*Psz + q)*3 + 0];
    spx[q]  = g_o[(q*Bsz + 0)*OUTN + 0];
    spy[q]  = g_o[(q*Bsz + 0)*OUTN + 1];
  } else {
    const float* xb = x + (size_t)(t*Psz)*3;
    spid[q] = xb[q*3+0]; spx[q] = xb[q*3+1]; spy[q] = xb[q*3+2];
  }
  __syncthreads();
  const float Rx = 0.2f, Ry = 0.2f, CELLF = 0.1f;
  float lx = spx[p]-Rx, rxb = spx[p]+Rx, by = spy[p]-Ry, ty = spy[p]+Ry;
  float ox = spx[q], oy = spy[q];
  bool inb   = (ox < rxb) && (ox >= lx) && (oy < ty) && (oy >= by);
  bool valid = (spid[p] != 0.f) && (spid[q] != 0.f) && (spid[p] != spid[q]);
  int cx = (int)floorf((ox - lx)/CELLF);
  int cy = (int)floorf((oy - by)/CELLF);
  int idx = cx + cy*4; idx = idx < 0 ? 0 : (idx > 15 ? 15 : idx);
  garr[q] = (inb && valid) ? (unsigned char)idx : (unsigned char)255;
  __syncthreads();
  if (q < G2N){
    int c = 0;
    for (int o = 0; o < Psz; o++) if (garr[o] == (unsigned char)q) c++;
    cnt[q] = c;
  }
  __syncthreads();
  if (q == 0){
    int s = 0; unsigned int act = 0;
    for (int g = 0; g < G2N; g++){ off[g] = s; if (cnt[g]) act |= (1u<<g); s += cnt[g]; }
    off[G2N] = s;
    g_active[slot*Psz + p] = act;
    for (int g = 0; g <= G2N; g++) g_off[(slot*Psz + p)*17 + g] = off[g];
  }
  __syncthreads();
  if (q < G2N){
    int w = off[q];
    for (int o = 0; o < Psz; o++)
      if (garr[o] == (unsigned char)q) g_list[(size_t)(slot*Psz + p)*Psz + (w++)] = (unsigned char)o;
  }
}

// ---- hsum build for one cell: EXACT dual-accumulator even/odd order (bit-exact) ----
__device__ __forceinline__ void build_cell(
    int g, float* __restrict__ hsb, int wl, int tx,
    const float4* __restrict__ cs4,
    const unsigned char* __restrict__ ls,
    const int* __restrict__ offs){
  #pragma unroll
  for (int i2 = 0; i2 < 8; i2++){
    int pl = wl*8 + i2;
    int s = offs[pl*17 + g], e = offs[pl*17 + g + 1];
    unsigned long long a0lo = 0ull, a0hi = 0ull, a1lo = 0ull, a1hi = 0ull;
    int j = s;
    for (; j+1 < e; j += 2){
      ulonglong2 v0 = *(const ulonglong2*)(cs4 + (int)ls[pl*Psz + j]*32 + tx);
      ulonglong2 v1 = *(const ulonglong2*)(cs4 + (int)ls[pl*Psz + j+1]*32 + tx);
      ADD2(a0lo, v0.x); ADD2(a0hi, v0.y);
      ADD2(a1lo, v1.x); ADD2(a1hi, v1.y);
    }
    if (j < e){
      ulonglong2 v0 = *(const ulonglong2*)(cs4 + (int)ls[pl*Psz + j]*32 + tx);
      ADD2(a0lo, v0.x); ADD2(a0hi, v0.y);
    }
    ADD2(a0lo, a1lo); ADD2(a0hi, a1hi);
    *(ulonglong2*)(hsb + pl*132 + tx*4) = make_ulonglong2(a0lo, a0hi);
  }
}

// ---------------- fused: hsum||socGEMM pipeline + e + LSTM + c,h (R11-proven) ----------------
#define PT     64
#define HS_STR 132
#define ZS_STR 196
#define WS2    388
__global__ void __launch_bounds__(512, 1) k_fused(
    const float* __restrict__ x,
    const float* __restrict__ bsoc,
    const float* __restrict__ Win,
    const float* __restrict__ bin,
    const float* __restrict__ bih,
    const float* __restrict__ bhh,
    int t, int pred, int slot){
  extern __shared__ float dyn[];
  float* cs  = dyn;                        // 256*128 floats = 128 KB (phase A)
  float* hs0 = dyn + Psz*HIDN;             // 64*132 floats
  float* hs1 = hs0 + PT*HS_STR;            // 64*132 floats
  // phase B overlays (cs/hs dead):
  float* zs     = dyn;                     // 64*196 floats
  float* wstage = dyn + PT*ZS_STR;         // 16*388 floats
  float* gsum   = wstage + 16*WS2;         // 64*388 floats
  __shared__ unsigned char ls[PT*Psz];     // 16 KB neighbor lists
  __shared__ int offs[PT*(G2N+1)];
  __shared__ int gl[G2N];
  __shared__ int s_ng;

  int b = blockIdx.x, pbase = blockIdx.y*PT;
  int tid = threadIdx.x;
  float4* cs4 = (float4*)cs;

  // load c[:,b,:] (all 256 p rows for this b)
  for (int i = tid; i < Psz*HIDN/4; i += 512){
    int o = i>>5, q = i&31;
    cs4[i] = *(const float4*)(g_c + ((size_t)o*Bsz + b)*HIDN + q*4);
  }
  // neighbor lists + offsets for this p-tile (slot-indexed, contiguous copy)
  for (int i = tid; i < PT*Psz/16; i += 512)
    ((uint4*)ls)[i] = ((const uint4*)(g_list + (size_t)(slot*Psz + pbase)*Psz))[i];
  for (int i = tid; i < PT*(G2N+1); i += 512)
    offs[i] = g_off[(slot*Psz + pbase)*17 + i];
  if (tid == 0){
    unsigned int u = 0;
    for (int pp = 0; pp < PT; pp++) u |= g_active[slot*Psz + pbase + pp];
    int n = 0;
    for (int g = 0; g < G2N; g++) if ((u>>g)&1u) gl[n++] = g;
    s_ng = n;
  }
  __syncthreads();
  int ng = s_ng;

  int tx = tid & 31, wid = tid >> 5;    // 16 warps
  int group = wid >> 3, wl = wid & 7;   // group 0: GEMM, group 1: producer
  int n0 = tx*4, m0 = wl*8;
  unsigned long long acc01[8], acc23[8];
  #pragma unroll
  for (int i = 0; i < 8; i++){ acc01[i] = 0ull; acc23[i] = 0ull; }

  if (ng > 0){
    if (group == 1) build_cell(gl[0], hs0, wl, tx, cs4, ls, offs);
    __syncthreads();
    for (int gi = 0; gi < ng; gi++){
      if (group == 0){
        const float* hsb = (gi & 1) ? hs1 : hs0;
        const float* Wg = g_Wt + (size_t)gl[gi]*128*HIDN + n0;
        #pragma unroll 2
        for (int kc = 0; kc < 8; kc++){
          #pragma unroll
          for (int kq = 0; kq < 4; kq++){
            float4 hv[8];
            #pragma unroll
            for (int i = 0; i < 8; i++)
              hv[i] = *(const float4*)(hsb + (m0+i)*HS_STR + kc*16 + kq*4);
            #pragma unroll
            for (int kk = 0; kk < 4; kk++){
              ulonglong2 wp = *(const ulonglong2*)(Wg + (size_t)(kc*16 + kq*4 + kk)*HIDN);
              #pragma unroll
              for (int i = 0; i < 8; i++){
                float h = ((const float*)&hv[i])[kk];
                unsigned long long h2;
                PACK2(h2, h);
                FMA2(acc01[i], h2, wp.x);
                FMA2(acc23[i], h2, wp.y);
              }
            }
          }
        }
      } else if (gi + 1 < ng){
        build_cell(gl[gi+1], ((gi+1) & 1) ? hs1 : hs0, wl, tx, cs4, ls, offs);
      }
      __syncthreads();
    }
  }

  // ================= Phase B =================
  // B1: e = relu(pos @ Win^T + bin) -> zs[:,0:64]
  for (int i2 = tid; i2 < PT*MIDN; i2 += 512){
    int mm = i2 >> 6, j = i2 & 63;
    int p = pbase + mm;
    int r = p*Bsz + b;
    float px, py;
    if (pred){ px = g_o[r*OUTN+0]; py = g_o[r*OUTN+1]; }
    else {
      const float* xr = x + (size_t)(((b*Ssz)+t)*Psz + p)*3;
      px = xr[1]; py = xr[2];
    }
    float v = px*Win[j*2+0] + py*Win[j*2+1] + bin[j];
    zs[mm*ZS_STR + j] = v > 0.f ? v : 0.f;
  }
  // B1b: a = relu(acc + b_soc) -> zs[:,64:192]
  if (group == 0){
    float4 bv = *(const float4*)(bsoc + n0);
    #pragma unroll
    for (int i = 0; i < 8; i++){
      float a0, a1, a2, a3;
      UNPACK2(a0, a1, acc01[i]);
      UNPACK2(a2, a3, acc23[i]);
      float4 o;
      o.x = fmaxf(a0 + bv.x, 0.f);
      o.y = fmaxf(a1 + bv.y, 0.f);
      o.z = fmaxf(a2 + bv.z, 0.f);
      o.w = fmaxf(a3 + bv.w, 0.f);
      *(float4*)(zs + (m0+i)*ZS_STR + MIDN + n0) = o;
    }
  }
  __syncthreads();

  // B2: LSTM gate GEMM: gsum[row][jj] = sum_{k=0..191} zs[row][k] * Wt2[k][jj]
  {
    int jpg = tid & 63, rowg = tid >> 6;
    int j0 = jpg*6, m2 = rowg*8;
    unsigned long long lacc[24];
    #pragma unroll
    for (int i = 0; i < 24; i++) lacc[i] = 0ull;
    for (int kc = 0; kc < 12; kc++){
      #pragma unroll
      for (int s3 = 0; s3 < 3; s3++){
        int idx = s3*512 + tid;           // 0..1535
        int kk = idx / 96, v4 = idx % 96;
        *(float4*)(wstage + kk*WS2 + v4*4) =
          *(const float4*)(g_Wt2 + (size_t)(kc*16 + kk)*384 + v4*4);
      }
      __syncthreads();
      #pragma unroll 4
      for (int kk = 0; kk < 16; kk++){
        int k = kc*16 + kk;
        unsigned long long h2[8];
        #pragma unroll
        for (int i = 0; i < 8; i++){
          float hv = zs[(m2+i)*ZS_STR + k];
          PACK2(h2[i], hv);
        }
        #pragma unroll
        for (int jj = 0; jj < 3; jj++){
          unsigned long long w2 = *(const unsigned long long*)(wstage + kk*WS2 + j0 + 2*jj);
          #pragma unroll
          for (int i = 0; i < 8; i++)
            FMA2(lacc[i*3+jj], h2[i], w2);
        }
      }
      __syncthreads();
    }
    #pragma unroll
    for (int i = 0; i < 8; i++)
      #pragma unroll
      for (int jj = 0; jj < 3; jj++)
        *(unsigned long long*)(gsum + (m2+i)*WS2 + j0 + 2*jj) = lacc[i*3+jj];
  }
  __syncthreads();

  // B3: gates -> c, h  (exact formulas/order)
  for (int idx = tid; idx < PT*HIDN; idx += 512){
    int row = idx >> 7, jH = idx & 127;
    float ai = gsum[row*WS2 + jH];
    float ag = gsum[row*WS2 + 128 + jH];
    float ao = gsum[row*WS2 + 256 + jH];
    float bi_ = bih[jH]       + bhh[jH];
    float bg_ = bih[256 + jH] + bhh[256 + jH];
    float bo_ = bih[384 + jH] + bhh[384 + jH];
    float ci = sigf(ai+bi_)*tanhf(ag+bg_);
    float hh = sigf(ao+bo_)*tanhf(ci);
    int r = (pbase + row)*Bsz + b;
    g_c[(size_t)r*HIDN + jH] = ci;
    g_h[(size_t)r*HIDN + jH] = hh;
  }
}

// ---------------- output head o = h @ Wout^T + bout (+ op write, + xp write) ----------------
__global__ void k_out(const float* __restrict__ Wout, const float* __restrict__ bout,
                      const float* __restrict__ x, float* __restrict__ out,
                      int wr_op, int kstep, int wr_xp, int xpk){
  int warp = threadIdx.x >> 5, lane = threadIdx.x & 31;
  int r = blockIdx.x*8 + warp;
  float hv[4];
  #pragma unroll
  for (int i = 0; i < 4; i++) hv[i] = g_h[(size_t)r*HIDN + lane + i*32];
  float res[5];
  #pragma unroll
  for (int c = 0; c < 5; c++){
    float s = 0.f;
    #pragma unroll
    for (int i = 0; i < 4; i++) s += hv[i]*__ldg(Wout + c*HIDN + lane + i*32);
    #pragma unroll
    for (int d = 16; d > 0; d >>= 1) s += __shfl_xor_sync(0xffffffffu, s, d);
    res[c] = s + bout[c];
  }
  if (lane == 0){
    int b = r & 31, p = r >> 5;
    #pragma unroll
    for (int c = 0; c < 5; c++){
      g_o[r*OUTN + c] = res[c];
      if (wr_op)
        out[(size_t)XP_ELEMS + ((size_t)(b*PREDN + kstep)*Psz + p)*OUTN + c] = res[c];
    }
    if (wr_xp){
      float pid = x[((size_t)(b*Ssz + Ssz-1)*Psz + p)*3 + 0];
      size_t base = ((size_t)(b*PREDN + xpk)*Psz + p)*3;
      out[base+0] = pid;
      out[base+1] = res[0];
      out[base+2] = res[1];
    }
  }
}

// ---------------- launch ----------------
extern "C" void kernel_launch(void* const* d_in, const int* in_sizes, int n_in,
                              void* d_out, int out_size){
  const float* x    = (const float*)d_in[0];
  const float* Win  = (const float*)d_in[1];
  const float* bin  = (const float*)d_in[2];
  const float* Wsoc = (const float*)d_in[3];
  const float* bsoc = (const float*)d_in[4];
  const float* bprev= (const float*)d_in[5];
  const float* Wih  = (const float*)d_in[6];
  const float* bih  = (const float*)d_in[7];
  const float* bhh  = (const float*)d_in[8];
  const float* Wout = (const float*)d_in[9];
  const float* bout = (const float*)d_in[10];
  float* out = (float*)d_out;

  const int DYN_A = (Psz*HIDN + 2*PT*HS_STR)*(int)sizeof(float);
  const int DYN_B = (PT*ZS_STR + 16*WS2 + PT*WS2)*(int)sizeof(float);
  const int DYN = DYN_A > DYN_B ? DYN_A : DYN_B;
  cudaFuncSetAttribute(k_fused, cudaFuncAttributeMaxDynamicSharedMemorySize, DYN);

  k_init<<<(RROWS*HIDN + 255)/256, 256>>>(bprev);
  k_wt<<<(HIDN*2048 + 255)/256, 256>>>(Wsoc);
  k_wt2<<<(ZC*384 + 255)/256, 256>>>(Wih);
  // all 8 obs masks in ONE launch (independent of recurrence)
  k_mask<<<dim3(Psz, OBSN), Psz>>>(x, 0, 0);
  for (int t = 0; t < OBSN; t++){
    k_fused<<<dim3(Bsz, Psz/PT), 512, DYN>>>(x, bsoc, Win, bin, bih, bhh, t, 0, t);
    if (t == OBSN-1)
      k_out<<<RROWS/8, 256>>>(Wout, bout, x, out, 0, 0, 1, 0);   // g_o + xp[0]
  }
  for (int k = 0; k < PREDN; k++){
    k_mask<<<dim3(Psz, 1), Psz>>>(x, 0, 1);
    k_fused<<<dim3(Bsz, Psz/PT), 512, DYN>>>(x, bsoc, Win, bin, bih, bhh, 0, 1, 0);
    k_out<<<RROWS/8, 256>>>(Wout, bout, x, out, 1, k, (k < PREDN-1) ? 1 : 0, k+1);
  }
}

// round 14
// speedup vs baseline: 1.0599x; 1.0297x over previous
#include <cuda_runtime.h>
#include <math.h>

#define Bsz   32
#define Ssz   20
#define Psz   256
#define HIDN  128
#define MIDN  64
#define G2N   16
#define OBSN  8
#define PREDN 12
#define OUTN  5
#define RROWS (Psz*Bsz)          // 8192 rows, r = p*32 + b  (p-major)
#define ZC    (MIDN+HIDN)        // 192
#define XP_ELEMS (Bsz*PREDN*Psz*3)   // 294912

// ---- packed fp32x2 helpers (sm_100+): bit-exact per-lane f32 ops ----
#define PACK2(d, s)      asm("mov.b64 %0, {%1, %1};" : "=l"(d) : "f"(s))
#define UNPACK2(lo,hi,s) asm("mov.b64 {%0, %1}, %2;" : "=f"(lo), "=f"(hi) : "l"(s))
#define FMA2(d, a, b)    asm("fma.rn.f32x2 %0, %1, %2, %0;" : "+l"(d) : "l"(a), "l"(b))
#define ADD2(d, a)       asm("add.rn.f32x2 %0, %0, %1;" : "+l"(d) : "l"(a))

// ---------------- device scratch ----------------
__device__ float g_c[RROWS*HIDN];          // carry (cell state), 4 MB
__device__ float g_h[RROWS*HIDN];          // hidden h, 4 MB
__device__ float g_o[RROWS*OUTN];          // last output
__device__ float g_Wt[2048*HIDN];          // W_soc transposed [k][n], 1 MB
__device__ float g_Wt2[ZC*384];            // W_ih (i,g,o rows) transposed [k][384]
__device__ unsigned char g_list[OBSN*Psz*Psz];  // per-slot per-p neighbor ids
__device__ int g_off[OBSN*Psz*17];              // per-slot per-p per-cell offsets
__device__ unsigned int g_active[OBSN*Psz];     // per-slot per-p active bitmask

__device__ __forceinline__ float sigf(float x){ return 1.f/(1.f+expf(-x)); }

// ---------------- init carry = relu(b_prev) broadcast ----------------
__global__ void k_init(const float* __restrict__ bprev){
  int i = blockIdx.x*256 + threadIdx.x;
  if (i < RROWS*HIDN){ float v = bprev[i & (HIDN-1)]; g_c[i] = v > 0.f ? v : 0.f; }
}

// ---------------- one-time transpose of W_soc [128][2048] -> g_Wt [2048][128] ----------------
__global__ void k_wt(const float* __restrict__ Wsoc){
  int i = blockIdx.x*256 + threadIdx.x;     // i over 128*2048
  if (i < HIDN*2048){
    int n = i >> 11, k = i & 2047;
    g_Wt[k*HIDN + n] = Wsoc[i];
  }
}

// ---------------- one-time transpose of W_ih (rows i,g,o) -> g_Wt2 [192][384] ----------------
__global__ void k_wt2(const float* __restrict__ Wih){
  int i = blockIdx.x*256 + threadIdx.x;     // i over 192*384
  if (i < ZC*384){
    int k = i / 384, jj = i % 384;
    int row = (jj < 128) ? jj : jj + 128;
    g_Wt2[k*384 + jj] = Wih[(size_t)row*ZC + k];
  }
}

// ---------------- mask: ballot + cross-warp prefix, ORDER-EXACT vs serial scan ----------------
// Block = one p (256 threads). List order per cell = (warp asc, lane asc) = q asc,
// identical to the serial scan. grid.y batches steps; slot = pred ? 0 : t.
__global__ void k_mask(const float* __restrict__ x, int t_base, int pred){
  __shared__ float spid[Psz], spx[Psz], spy[Psz];
  __shared__ int cntm[8*16];     // [warp][g]
  __shared__ int offg[17];       // cell starts (exclusive prefix)
  __shared__ int wbase[8*16];    // per-warp base within cell
  int p = blockIdx.x, q = threadIdx.x;
  int t = t_base + blockIdx.y;
  int slot = pred ? 0 : t;
  if (pred){
    spid[q] = x[((size_t)(Ssz-1)*Psz + q)*3 + 0];
    spx[q]  = g_o[(q*Bsz + 0)*OUTN + 0];
    spy[q]  = g_o[(q*Bsz + 0)*OUTN + 1];
  } else {
    const float* xb = x + (size_t)(t*Psz)*3;
    spid[q] = xb[q*3+0]; spx[q] = xb[q*3+1]; spy[q] = xb[q*3+2];
  }
  __syncthreads();
  const float Rx = 0.2f, Ry = 0.2f, CELLF = 0.1f;
  float lx = spx[p]-Rx, rxb = spx[p]+Rx, by = spy[p]-Ry, ty = spy[p]+Ry;
  float ox = spx[q], oy = spy[q];
  bool inb   = (ox < rxb) && (ox >= lx) && (oy < ty) && (oy >= by);
  bool valid = (spid[p] != 0.f) && (spid[q] != 0.f) && (spid[p] != spid[q]);
  int cx = (int)floorf((ox - lx)/CELLF);
  int cy = (int)floorf((oy - by)/CELLF);
  int idx = cx + cy*4; idx = idx < 0 ? 0 : (idx > 15 ? 15 : idx);
  int myg = (inb && valid) ? idx : 255;
  int w = q >> 5, lane = q & 31;
  unsigned int lt = (1u << lane) - 1u;
  // per-warp per-cell counts
  #pragma unroll
  for (int g = 0; g < 16; g++){
    unsigned int m = __ballot_sync(0xffffffffu, myg == g);
    if (lane == 0) cntm[w*16 + g] = __popc(m);
  }
  __syncthreads();
  if (q == 0){
    int s = 0; unsigned int act = 0;
    #pragma unroll
    for (int g = 0; g < 16; g++){
      offg[g] = s;
      int c = 0;
      #pragma unroll
      for (int w2 = 0; w2 < 8; w2++) c += cntm[w2*16 + g];
      if (c) act |= (1u << g);
      s += c;
    }
    offg[16] = s;
    g_active[slot*Psz + p] = act;
  }
  __syncthreads();
  if (q < 17) g_off[(slot*Psz + p)*17 + q] = offg[q];
  if (q < 128){
    int w2 = q >> 4, g = q & 15;
    int bse = offg[g];
    for (int w3 = 0; w3 < w2; w3++) bse += cntm[w3*16 + g];
    wbase[w2*16 + g] = bse;
  }
  __syncthreads();
  #pragma unroll
  for (int g = 0; g < 16; g++){
    unsigned int m = __ballot_sync(0xffffffffu, myg == g);
    if (myg == g)
      g_list[(size_t)(slot*Psz + p)*Psz + wbase[w*16 + g] + __popc(m & lt)] = (unsigned char)q;
  }
}

// ---- hsum build for one cell: EXACT dual-accumulator even/odd order (bit-exact) ----
__device__ __forceinline__ void build_cell(
    int g, float* __restrict__ hsb, int wl, int tx,
    const float4* __restrict__ cs4,
    const unsigned char* __restrict__ ls,
    const int* __restrict__ offs){
  #pragma unroll
  for (int i2 = 0; i2 < 8; i2++){
    int pl = wl*8 + i2;
    int s = offs[pl*17 + g], e = offs[pl*17 + g + 1];
    unsigned long long a0lo = 0ull, a0hi = 0ull, a1lo = 0ull, a1hi = 0ull;
    int j = s;
    for (; j+1 < e; j += 2){
      ulonglong2 v0 = *(const ulonglong2*)(cs4 + (int)ls[pl*Psz + j]*32 + tx);
      ulonglong2 v1 = *(const ulonglong2*)(cs4 + (int)ls[pl*Psz + j+1]*32 + tx);
      ADD2(a0lo, v0.x); ADD2(a0hi, v0.y);
      ADD2(a1lo, v1.x); ADD2(a1hi, v1.y);
    }
    if (j < e){
      ulonglong2 v0 = *(const ulonglong2*)(cs4 + (int)ls[pl*Psz + j]*32 + tx);
      ADD2(a0lo, v0.x); ADD2(a0hi, v0.y);
    }
    ADD2(a0lo, a1lo); ADD2(a0hi, a1hi);
    *(ulonglong2*)(hsb + pl*132 + tx*4) = make_ulonglong2(a0lo, a0hi);
  }
}

// ---------------- fused: hsum||socGEMM pipeline + e + LSTM + c,h (R11-proven) ----------------
#define PT     64
#define HS_STR 132
#define ZS_STR 196
#define WS2    388
__global__ void __launch_bounds__(512, 1) k_fused(
    const float* __restrict__ x,
    const float* __restrict__ bsoc,
    const float* __restrict__ Win,
    const float* __restrict__ bin,
    const float* __restrict__ bih,
    const float* __restrict__ bhh,
    int t, int pred, int slot){
  extern __shared__ float dyn[];
  float* cs  = dyn;                        // 256*128 floats = 128 KB (phase A)
  float* hs0 = dyn + Psz*HIDN;             // 64*132 floats
  float* hs1 = hs0 + PT*HS_STR;            // 64*132 floats
  // phase B overlays (cs/hs dead):
  float* zs     = dyn;                     // 64*196 floats
  float* wstage = dyn + PT*ZS_STR;         // 16*388 floats
  float* gsum   = wstage + 16*WS2;         // 64*388 floats
  __shared__ unsigned char ls[PT*Psz];     // 16 KB neighbor lists
  __shared__ int offs[PT*(G2N+1)];
  __shared__ int gl[G2N];
  __shared__ int s_ng;

  int b = blockIdx.x, pbase = blockIdx.y*PT;
  int tid = threadIdx.x;
  float4* cs4 = (float4*)cs;

  // load c[:,b,:] (all 256 p rows for this b)
  for (int i = tid; i < Psz*HIDN/4; i += 512){
    int o = i>>5, q = i&31;
    cs4[i] = *(const float4*)(g_c + ((size_t)o*Bsz + b)*HIDN + q*4);
  }
  // neighbor lists + offsets for this p-tile (slot-indexed, contiguous copy)
  for (int i = tid; i < PT*Psz/16; i += 512)
    ((uint4*)ls)[i] = ((const uint4*)(g_list + (size_t)(slot*Psz + pbase)*Psz))[i];
  for (int i = tid; i < PT*(G2N+1); i += 512)
    offs[i] = g_off[(slot*Psz + pbase)*17 + i];
  if (tid == 0){
    unsigned int u = 0;
    for (int pp = 0; pp < PT; pp++) u |= g_active[slot*Psz + pbase + pp];
    int n = 0;
    for (int g = 0; g < G2N; g++) if ((u>>g)&1u) gl[n++] = g;
    s_ng = n;
  }
  __syncthreads();
  int ng = s_ng;

  int tx = tid & 31, wid = tid >> 5;    // 16 warps
  int group = wid >> 3, wl = wid & 7;   // group 0: GEMM, group 1: producer
  int n0 = tx*4, m0 = wl*8;
  unsigned long long acc01[8], acc23[8];
  #pragma unroll
  for (int i = 0; i < 8; i++){ acc01[i] = 0ull; acc23[i] = 0ull; }

  if (ng > 0){
    if (group == 1) build_cell(gl[0], hs0, wl, tx, cs4, ls, offs);
    __syncthreads();
    for (int gi = 0; gi < ng; gi++){
      if (group == 0){
        const float* hsb = (gi & 1) ? hs1 : hs0;
        const float* Wg = g_Wt + (size_t)gl[gi]*128*HIDN + n0;
        #pragma unroll 2
        for (int kc = 0; kc < 8; kc++){
          #pragma unroll
          for (int kq = 0; kq < 4; kq++){
            float4 hv[8];
            #pragma unroll
            for (int i = 0; i < 8; i++)
              hv[i] = *(const float4*)(hsb + (m0+i)*HS_STR + kc*16 + kq*4);
            #pragma unroll
            for (int kk = 0; kk < 4; kk++){
              ulonglong2 wp = *(const ulonglong2*)(Wg + (size_t)(kc*16 + kq*4 + kk)*HIDN);
              #pragma unroll
              for (int i = 0; i < 8; i++){
                float h = ((const float*)&hv[i])[kk];
                unsigned long long h2;
                PACK2(h2, h);
                FMA2(acc01[i], h2, wp.x);
                FMA2(acc23[i], h2, wp.y);
              }
            }
          }
        }
      } else if (gi + 1 < ng){
        build_cell(gl[gi+1], ((gi+1) & 1) ? hs1 : hs0, wl, tx, cs4, ls, offs);
      }
      __syncthreads();
    }
  }

  // ================= Phase B =================
  // B1: e = relu(pos @ Win^T + bin) -> zs[:,0:64]
  for (int i2 = tid; i2 < PT*MIDN; i2 += 512){
    int mm = i2 >> 6, j = i2 & 63;
    int p = pbase + mm;
    int r = p*Bsz + b;
    float px, py;
    if (pred){ px = g_o[r*OUTN+0]; py = g_o[r*OUTN+1]; }
    else {
      const float* xr = x + (size_t)(((b*Ssz)+t)*Psz + p)*3;
      px = xr[1]; py = xr[2];
    }
    float v = px*Win[j*2+0] + py*Win[j*2+1] + bin[j];
    zs[mm*ZS_STR + j] = v > 0.f ? v : 0.f;
  }
  // B1b: a = relu(acc + b_soc) -> zs[:,64:192]
  if (group == 0){
    float4 bv = *(const float4*)(bsoc + n0);
    #pragma unroll
    for (int i = 0; i < 8; i++){
      float a0, a1, a2, a3;
      UNPACK2(a0, a1, acc01[i]);
      UNPACK2(a2, a3, acc23[i]);
      float4 o;
      o.x = fmaxf(a0 + bv.x, 0.f);
      o.y = fmaxf(a1 + bv.y, 0.f);
      o.z = fmaxf(a2 + bv.z, 0.f);
      o.w = fmaxf(a3 + bv.w, 0.f);
      *(float4*)(zs + (m0+i)*ZS_STR + MIDN + n0) = o;
    }
  }
  __syncthreads();

  // B2: LSTM gate GEMM: gsum[row][jj] = sum_{k=0..191} zs[row][k] * Wt2[k][jj]
  {
    int jpg = tid & 63, rowg = tid >> 6;
    int j0 = jpg*6, m2 = rowg*8;
    unsigned long long lacc[24];
    #pragma unroll
    for (int i = 0; i < 24; i++) lacc[i] = 0ull;
    for (int kc = 0; kc < 12; kc++){
      #pragma unroll
      for (int s3 = 0; s3 < 3; s3++){
        int idx = s3*512 + tid;           // 0..1535
        int kk = idx / 96, v4 = idx % 96;
        *(float4*)(wstage + kk*WS2 + v4*4) =
          *(const float4*)(g_Wt2 + (size_t)(kc*16 + kk)*384 + v4*4);
      }
      __syncthreads();
      #pragma unroll 4
      for (int kk = 0; kk < 16; kk++){
        int k = kc*16 + kk;
        unsigned long long h2[8];
        #pragma unroll
        for (int i = 0; i < 8; i++){
          float hv = zs[(m2+i)*ZS_STR + k];
          PACK2(h2[i], hv);
        }
        #pragma unroll
        for (int jj = 0; jj < 3; jj++){
          unsigned long long w2 = *(const unsigned long long*)(wstage + kk*WS2 + j0 + 2*jj);
          #pragma unroll
          for (int i = 0; i < 8; i++)
            FMA2(lacc[i*3+jj], h2[i], w2);
        }
      }
      __syncthreads();
    }
    #pragma unroll
    for (int i = 0; i < 8; i++)
      #pragma unroll
      for (int jj = 0; jj < 3; jj++)
        *(unsigned long long*)(gsum + (m2+i)*WS2 + j0 + 2*jj) = lacc[i*3+jj];
  }
  __syncthreads();

  // B3: gates -> c, h  (exact formulas/order)
  for (int idx = tid; idx < PT*HIDN; idx += 512){
    int row = idx >> 7, jH = idx & 127;
    float ai = gsum[row*WS2 + jH];
    float ag = gsum[row*WS2 + 128 + jH];
    float ao = gsum[row*WS2 + 256 + jH];
    float bi_ = bih[jH]       + bhh[jH];
    float bg_ = bih[256 + jH] + bhh[256 + jH];
    float bo_ = bih[384 + jH] + bhh[384 + jH];
    float ci = sigf(ai+bi_)*tanhf(ag+bg_);
    float hh = sigf(ao+bo_)*tanhf(ci);
    int r = (pbase + row)*Bsz + b;
    g_c[(size_t)r*HIDN + jH] = ci;
    g_h[(size_t)r*HIDN + jH] = hh;
  }
}

// ---------------- output head o = h @ Wout^T + bout (+ op write, + xp write) ----------------
__global__ void k_out(const float* __restrict__ Wout, const float* __restrict__ bout,
                      const float* __restrict__ x, float* __restrict__ out,
                      int wr_op, int kstep, int wr_xp, int xpk){
  int warp = threadIdx.x >> 5, lane = threadIdx.x & 31;
  int r = blockIdx.x*8 + warp;
  float hv[4];
  #pragma unroll
  for (int i = 0; i < 4; i++) hv[i] = g_h[(size_t)r*HIDN + lane + i*32];
  float res[5];
  #pragma unroll
  for (int c = 0; c < 5; c++){
    float s = 0.f;
    #pragma unroll
    for (int i = 0; i < 4; i++) s += hv[i]*__ldg(Wout + c*HIDN + lane + i*32);
    #pragma unroll
    for (int d = 16; d > 0; d >>= 1) s += __shfl_xor_sync(0xffffffffu, s, d);
    res[c] = s + bout[c];
  }
  if (lane == 0){
    int b = r & 31, p = r >> 5;
    #pragma unroll
    for (int c = 0; c < 5; c++){
      g_o[r*OUTN + c] = res[c];
      if (wr_op)
        out[(size_t)XP_ELEMS + ((size_t)(b*PREDN + kstep)*Psz + p)*OUTN + c] = res[c];
    }
    if (wr_xp){
      float pid = x[((size_t)(b*Ssz + Ssz-1)*Psz + p)*3 + 0];
      size_t base = ((size_t)(b*PREDN + xpk)*Psz + p)*3;
      out[base+0] = pid;
      out[base+1] = res[0];
      out[base+2] = res[1];
    }
  }
}

// ---------------- launch ----------------
extern "C" void kernel_launch(void* const* d_in, const int* in_sizes, int n_in,
                              void* d_out, int out_size){
  const float* x    = (const float*)d_in[0];
  const float* Win  = (const float*)d_in[1];
  const float* bin  = (const float*)d_in[2];
  const float* Wsoc = (const float*)d_in[3];
  const float* bsoc = (const float*)d_in[4];
  const float* bprev= (const float*)d_in[5];
  const float* Wih  = (const float*)d_in[6];
  const float* bih  = (const float*)d_in[7];
  const float* bhh  = (const float*)d_in[8];
  const float* Wout = (const float*)d_in[9];
  const float* bout = (const float*)d_in[10];
  float* out = (float*)d_out;

  const int DYN_A = (Psz*HIDN + 2*PT*HS_STR)*(int)sizeof(float);
  const int DYN_B = (PT*ZS_STR + 16*WS2 + PT*WS2)*(int)sizeof(float);
  const int DYN = DYN_A > DYN_B ? DYN_A : DYN_B;
  cudaFuncSetAttribute(k_fused, cudaFuncAttributeMaxDynamicSharedMemorySize, DYN);

  k_init<<<(RROWS*HIDN + 255)/256, 256>>>(bprev);
  k_wt<<<(HIDN*2048 + 255)/256, 256>>>(Wsoc);
  k_wt2<<<(ZC*384 + 255)/256, 256>>>(Wih);
  // all 8 obs masks in ONE launch (independent of recurrence)
  k_mask<<<dim3(Psz, OBSN), Psz>>>(x, 0, 0);
  for (int t = 0; t < OBSN; t++){
    k_fused<<<dim3(Bsz, Psz/PT), 512, DYN>>>(x, bsoc, Win, bin, bih, bhh, t, 0, t);
    if (t == OBSN-1)
      k_out<<<RROWS/8, 256>>>(Wout, bout, x, out, 0, 0, 1, 0);   // g_o + xp[0]
  }
  for (int k = 0; k < PREDN; k++){
    k_mask<<<dim3(Psz, 1), Psz>>>(x, 0, 1);
    k_fused<<<dim3(Bsz, Psz/PT), 512, DYN>>>(x, bsoc, Win, bin, bih, bhh, 0, 1, 0);
    k_out<<<RROWS/8, 256>>>(Wout, bout, x, out, 1, k, (k < PREDN-1) ? 1 : 0, k+1);
  }
}